// round 16
// baseline (speedup 1.0000x reference)
#include <cuda_runtime.h>
#include <math.h>
#include <stdint.h>

// ---------------------------------------------------------------------------
// YOLO loss, fused single kernel (712 blocks x 256), templated per level.
// R16 = R15 + (a) acq_rel counter instead of __threadfence (no CCTL L1 flush),
// (b) per-warp obj_neg atomics (epilogue syncs 2->1), (c) positives spread
// one-pair-per-block on warp 7.
// ---------------------------------------------------------------------------

#define NBATCH 8
#define MTGT   64
#define NCLS   80
#define NCHAN  85
#define NPAIR  (3 * MTGT * 3)   // 576
#define MAXW   76
#define BMW    3
#define BMWORDS (NBATCH * MAXW * BMW)   // 1824 words

__device__ __constant__ float C_INV[3]  = {0.125f, 0.0625f, 0.03125f};
__device__ __constant__ float C_XYS[3]  = {1.2f, 1.1f, 1.05f};
__device__ __constant__ float C_AW[3][3] = {
    {1.5f, 2.375f, 5.0f},
    {2.25f, 4.75f, 4.5f},
    {4.4375f, 6.0f, 14.34375f}};
__device__ __constant__ float C_AH[3][3] = {
    {2.0f, 4.5f, 3.5f},
    {4.6875f, 3.4375f, 9.125f},
    {3.4375f, 7.59375f, 12.53125f}};

#define NBLK0  542
#define NBLK1  136
#define NBLK2  34
#define NBLK_TOTAL (NBLK0 + NBLK1 + NBLK2)   // 712

// fixed-point accumulators: [0]=iou, [1]=obj_pos, [2]=cls, [3]=obj_neg
__device__ long long g_acc[4] = {0, 0, 0, 0};
__device__ unsigned  g_done = 0;

#define FP_SCALE 1099511627776.0   // 2^40

__device__ __forceinline__ void acc_add(int q, double v) {
    atomicAdd((unsigned long long*)&g_acc[q],
              (unsigned long long)__double2ll_rn(v * FP_SCALE));
}

// acq_rel fetch-add: release prior (relaxed) atomics; acquire on read.
__device__ __forceinline__ unsigned atomic_add_acqrel(unsigned* p, unsigned v) {
    unsigned old;
    asm volatile("atom.acq_rel.gpu.global.add.u32 %0, [%1], %2;"
                 : "=r"(old) : "l"(p), "r"(v) : "memory");
    return old;
}

// ---------------------------------------------------------------------------
__device__ __forceinline__ float softplus_fast(float x) {
    return fmaxf(x, 0.0f) + __logf(1.0f + __expf(-fabsf(x)));
}

struct TPrep {
    float4 corn;
    float4 cwh;
    float  area;
    int    meta;   // bid | ti<<4 | tj<<12 | matchbits<<20
};

// EXACT fp32 (div by pow2 -> exact multiply), same op order as reference
__device__ __forceinline__ TPrep prep_one(int L, int t,
                                          const float* __restrict__ targets) {
    float inv = C_INV[L];
    float x1 = targets[t * 5 + 0] * inv;
    float y1 = targets[t * 5 + 1] * inv;
    float x2 = targets[t * 5 + 2] * inv;
    float y2 = targets[t * 5 + 3] * inv;
    int bid  = (int)targets[t * 5 + 4];

    float wx = x2 - x1, wy = y2 - y1;
    float cx = (x1 + x2) * 0.5f, cy = (y1 + y2) * 0.5f;
    int ti = (int)cx, tj = (int)cy;
    float tarea = wx * wy;

    float iou[3];
    #pragma unroll
    for (int a = 0; a < 3; ++a) {
        float aw = C_AW[L][a], ah = C_AH[L][a];
        float inter = fminf(aw, wx) * fminf(ah, wy);
        iou[a] = inter / ((aw * ah + tarea) - inter);   // IEEE div: threshold-critical
    }
    int best = 0;
    if (iou[1] > iou[best]) best = 1;
    if (iou[2] > iou[best]) best = 2;
    int mb = 0;
    #pragma unroll
    for (int a = 0; a < 3; ++a)
        if (iou[a] > 0.213f || a == best) mb |= (1 << a);

    TPrep p;
    p.corn = make_float4(cx - wx * 0.5f, cy - wy * 0.5f,
                         cx + wx * 0.5f, cy + wy * 0.5f);
    p.cwh  = make_float4(cx, cy, wx, wy);
    p.area = tarea;
    p.meta = bid | (ti << 4) | (tj << 12) | (mb << 20);
    return p;
}

// CIoU (forward)
__device__ __forceinline__ float ciou_f(
    float cx1, float cy1, float w1, float h1,
    float cx2, float cy2, float w2, float h2) {
    float b1x1 = cx1 - 0.5f * w1, b1x2 = cx1 + 0.5f * w1;
    float b1y1 = cy1 - 0.5f * h1, b1y2 = cy1 + 0.5f * h1;
    float b2x1 = cx2 - 0.5f * w2, b2x2 = cx2 + 0.5f * w2;
    float b2y1 = cy2 - 0.5f * h2, b2y2 = cy2 + 0.5f * h2;
    float iw = fminf(b1x2, b2x2) - fmaxf(b1x1, b2x1);
    float ih = fminf(b1y2, b2y2) - fmaxf(b1y1, b2y1);
    float inter = fmaxf(iw, 0.0f) * fmaxf(ih, 0.0f);
    float uni = w1 * h1 + w2 * h2 + 1e-16f - inter;
    float iou = inter / uni;
    float cw = fmaxf(b1x2, b2x2) - fminf(b1x1, b2x1);
    float ch = fmaxf(b1y2, b2y2) - fminf(b1y1, b2y1);
    float c2 = cw * cw + ch * ch + 1e-16f;
    float rho2 = (cx1 - cx2) * (cx1 - cx2) + (cy1 - cy2) * (cy1 - cy2);
    float d = atanf(w2 / h2) - atanf(w1 / h1);
    float v = (float)(4.0 / (M_PI * M_PI)) * d * d;
    float alpha = v / ((1.0f - iou) + v + 1e-16f);
    return iou - (rho2 / c2 + v * alpha);
}

// ---------------------------------------------------------------------------
struct SharedState {
    uint32_t bm[BMWORDS];        // 7.3 KB candidate bitmap
    float4 corn[MTGT];           // by target index (uncompacted)
    float  area[MTGT];
    int    key [MTGT];           // ti | tj<<8 | mb<<16
    int4   pf  [MTGT];           // tight candidate boxes
    int    bid [MTGT];
    uint32_t mask[NBATCH][2];    // per-batch membership (ballot-built)
};

// Per-level flow. All threads of a block share LVL (uniform syncs).
template<int W, int HW, int LVL>
__device__ __forceinline__ float level_flow(
    const float* __restrict__ pred,
    const float* __restrict__ targets,
    int blk, int tid, SharedState& ss) {

    constexpr float s = (LVL == 0) ? 1.2f : ((LVL == 1) ? 1.1f : 1.05f);
    constexpr float half_sm1 = 0.5f * (s - 1.0f);

    // ---- decode my cell and ISSUE the obj-logit load NOW --------------------
    int idx = blk * 256 + tid;
    bool incell = idx < 24 * HW;
    int lc = 0, x = 0, y = 0, a = 0, b = 0, chan = 0;
    float po = 0.0f;
    if (incell) {
        int plane = idx / HW;        // constant divisor -> mul-shift
        lc = idx - plane * HW;
        y = lc / W;
        x = lc - y * W;
        a = plane % 3;
        b = plane / 3;
        chan = plane * (NCHAN * HW);
        po = pred[chan + 4 * HW + lc];   // DRAM latency overlaps preamble
    }

    // ---- preamble phase A ------------------------------------------------------
    if (tid < MTGT) {
        TPrep myp = prep_one(LVL, tid, targets);
        int bb = myp.meta & 15;

        // TIGHT candidate box: IoU>0.7 => |pred_cx - t_cx| <= (3/14)*tw;
        // cell_x = pred_cx - bx with bx in [-0.1, 1.1].
        float tw = myp.cwh.z, th = myp.cwh.w;
        float cx = myp.cwh.x, cy = myp.cwh.y;
        int xlo = max(0,     (int)floorf(cx - 0.22f * tw - 1.2f));
        int xhi = min(W - 1, (int)ceilf (cx + 0.22f * tw + 0.2f));
        int ylo = max(0,     (int)floorf(cy - 0.22f * th - 1.2f));
        int yhi = min(W - 1, (int)ceilf (cy + 0.22f * th + 0.2f));

        ss.corn[tid] = myp.corn;
        ss.area[tid] = myp.area;
        ss.key [tid] = ((myp.meta >> 4) & 255) | (((myp.meta >> 12) & 255) << 8)
                     | (((myp.meta >> 20) & 7) << 16);
        ss.pf  [tid] = make_int4(xlo, xhi, ylo, yhi);
        ss.bid [tid] = bb;

        int word = tid >> 5;
        int lane = tid & 31;
        #pragma unroll
        for (int j = 0; j < NBATCH; ++j) {
            uint32_t m = __ballot_sync(0xFFFFFFFFu, bb == j);
            if (lane == j) ss.mask[j][word] = m;
        }
    } else {
        uint4* bm4 = reinterpret_cast<uint4*>(ss.bm);
        for (int i = tid - MTGT; i < BMWORDS / 4; i += 192)
            bm4[i] = make_uint4(0u, 0u, 0u, 0u);
    }
    __syncthreads();   // bitmap zeroed, lists + masks + boxes written

    // ---- preamble phase B: ALL 256 threads paint (target, row-quarter) ---------
    {
        int k = tid & 63;
        int q = tid >> 6;          // 0..3
        int4 bx4 = ss.pf[k];
        if (bx4.x <= bx4.y) {
            uint32_t* bmrow = ss.bm + ss.bid[k] * (MAXW * BMW);
            int w0 = bx4.x >> 5, w1 = bx4.y >> 5;
            for (int yy = bx4.z + q; yy <= bx4.w; yy += 4) {
                for (int ww = w0; ww <= w1; ++ww) {
                    int lob = (ww == w0) ? (bx4.x & 31) : 0;
                    int hib = (ww == w1) ? (bx4.y & 31) : 31;
                    uint32_t bits = (hib == 31) ? (~0u << lob)
                                                : (((1u << (hib + 1)) - 1u) & (~0u << lob));
                    atomicOr(&bmrow[yy * BMW + ww], bits);
                }
            }
        }
    }
    float sp = incell ? softplus_fast(po) : 0.0f;   // overlaps painting
    __syncthreads();   // bitmap ready

    // ---- dense cell --------------------------------------------------------------
    float local = 0.0f;
    if (incell) {
        bool zero = false;
        if ((ss.bm[(b * MAXW + y) * BMW + (x >> 5)] >> (x & 31)) & 1u) {
            float p0 = pred[chan + lc];
            float p1 = pred[chan + HW + lc];
            float p2 = pred[chan + 2 * HW + lc];
            float p3 = pred[chan + 3 * HW + lc];

            float bx = __fdividef(1.0f, 1.0f + __expf(-p0)) * s - half_sm1;
            float by = __fdividef(1.0f, 1.0f + __expf(-p1)) * s - half_sm1;
            float pw = __expf(p2) * C_AW[LVL][a];
            float ph = __expf(p3) * C_AH[LVL][a];

            float cxa = bx + (float)x;
            float cya = by + (float)y;
            float bx1 = cxa - 0.5f * pw, bx2 = cxa + 0.5f * pw;
            float by1 = cya - 0.5f * ph, by2 = cya + 0.5f * ph;
            float parea = pw * ph;

            int mykey = x | (y << 8);
            #pragma unroll
            for (int word = 0; word < 2 && !zero; ++word) {
                uint32_t m = ss.mask[b][word];
                int kbase = word << 5;
                while (m) {
                    int k = kbase + __ffs(m) - 1;
                    m &= m - 1u;
                    int4 pf = ss.pf[k];
                    if (x < pf.x || x > pf.y || y < pf.z || y > pf.w) continue;
                    int kk = ss.key[k];
                    if (((kk & 0xFFFF) == mykey) && ((kk >> (16 + a)) & 1)) { zero = true; break; }
                    float4 c  = ss.corn[k];
                    float ix = fminf(bx2, c.z) - fmaxf(bx1, c.x);
                    float iy = fminf(by2, c.w) - fmaxf(by1, c.y);
                    float inter = fmaxf(ix, 0.0f) * fmaxf(iy, 0.0f);
                    float uni   = (parea + ss.area[k] + 1e-16f) - inter;
                    if (inter > 0.7f * uni) { zero = true; break; }
                }
            }
        }
        if (!zero) local = sp;
    }
    return local;
}

// ---------------------------------------------------------------------------
__global__ void __launch_bounds__(256, 8) yolo_fused_kernel(
    const float* __restrict__ pred0,
    const float* __restrict__ pred1,
    const float* __restrict__ pred2,
    const float* __restrict__ targets,
    const int*   __restrict__ cats,
    float* __restrict__ out) {

    int tid  = threadIdx.x;
    int lane = tid & 31;
    int wid  = tid >> 5;

    __shared__ SharedState ss;

    // ---- per-level dense flow (uniform branch per block) ----------------------
    float local;
    if (blockIdx.x >= NBLK0 + NBLK1)
        local = level_flow<19, 361, 2>(pred2, targets,
                                       blockIdx.x - (NBLK0 + NBLK1), tid, ss);
    else if (blockIdx.x >= NBLK0)
        local = level_flow<38, 1444, 1>(pred1, targets, blockIdx.x - NBLK0, tid, ss);
    else
        local = level_flow<76, 5776, 0>(pred0, targets, blockIdx.x, tid, ss);

    // ---- obj_neg: warp reduce + direct deterministic integer atomic ------------
    {
        float v = local;
        #pragma unroll
        for (int o = 16; o > 0; o >>= 1)
            v += __shfl_down_sync(0xFFFFFFFFu, v, o);
        if (lane == 0) acc_add(3, (double)v);
    }

    // ---- positives: one (L,t,a) pair per block, handled by warp 7 --------------
    if (blockIdx.x < NPAIR && wid == 7) {
        int gw  = blockIdx.x;
        int FL  = gw / (MTGT * 3);
        int rem = gw % (MTGT * 3);
        int t   = rem / 3;
        int a2  = rem % 3;

        TPrep pp = prep_one(FL, t, targets);   // uniform across lanes
        bool matched = (pp.meta >> (20 + a2)) & 1;

        if (matched) {
            int bid = pp.meta & 15;
            int ti  = (pp.meta >> 4) & 255;
            int tj  = (pp.meta >> 12) & 255;
            const float* fp = (FL == 0) ? pred0 : ((FL == 1) ? pred1 : pred2);
            int fw  = (FL == 0) ? 76 : ((FL == 1) ? 38 : 19);
            int fhw = fw * fw;
            int base = ((bid * 3 + a2) * NCHAN) * fhw + tj * fw + ti;

            float cls_acc = 0.0f;
            int cat = cats[t] - 1;
            for (int c = lane; c < NCLS; c += 32) {
                float xl  = fp[base + (5 + c) * fhw];
                float bce = softplus_fast(xl);
                if (c == cat) bce -= xl;
                cls_acc += bce;
            }
            #pragma unroll
            for (int o = 16; o > 0; o >>= 1)
                cls_acc += __shfl_down_sync(0xFFFFFFFFu, cls_acc, o);

            if (lane == 0) {
                float fs  = C_XYS[FL];
                float fhs = 0.5f * (fs - 1.0f);
                float p0 = fp[base];
                float p1 = fp[base + fhw];
                float p2 = fp[base + 2 * fhw];
                float p3 = fp[base + 3 * fhw];
                float pob = fp[base + 4 * fhw];

                float bx = __fdividef(1.0f, 1.0f + __expf(-p0)) * fs - fhs;
                float by = __fdividef(1.0f, 1.0f + __expf(-p1)) * fs - fhs;
                float pw = __expf(p2) * C_AW[FL][a2];
                float ph = __expf(p3) * C_AH[FL][a2];

                float fx = pp.cwh.x - (float)ti;
                float fy = pp.cwh.y - (float)tj;
                double iou_d = (double)(1.0f - ciou_f(bx, by, pw, ph, fx, fy,
                                                      pp.cwh.z, pp.cwh.w));
                double obj_d = (double)(softplus_fast(pob) - pob);
                acc_add(0, iou_d);
                acc_add(1, obj_d);
                acc_add(2, (double)cls_acc);
            }
        }
    }

    // ---- block completion: acq_rel counter (no L1-flushing fence) ---------------
    __syncthreads();   // all warps of this block have issued their acc atomics
    if (tid == 0) {
        unsigned old = atomic_add_acqrel(&g_done, 1u);
        if (old == NBLK_TOTAL - 1) {
            // acquire above makes all released acc atomics visible
            volatile long long* acc = g_acc;
            double iou = (double)acc[0] / FP_SCALE;
            double obj = (double)acc[1] / FP_SCALE;
            double cls = (double)acc[2] / FP_SCALE;
            double neg = (double)acc[3] / FP_SCALE;
            out[0] = (float)(0.07 * iou);
            out[1] = (float)(obj + neg);
            out[2] = (float)(cls);
            g_acc[0] = 0; g_acc[1] = 0; g_acc[2] = 0; g_acc[3] = 0;
            __threadfence();       // publish resets before counter reset
            g_done = 0;
        }
    }
}

// ---------------------------------------------------------------------------
extern "C" void kernel_launch(void* const* d_in, const int* in_sizes, int n_in,
                              void* d_out, int out_size) {
    const float* pred0   = (const float*)d_in[0];
    const float* pred1   = (const float*)d_in[1];
    const float* pred2   = (const float*)d_in[2];
    const float* targets = (const float*)d_in[3];
    const int*   cats    = (const int*)  d_in[4];
    float* out = (float*)d_out;

    yolo_fused_kernel<<<NBLK_TOTAL, 256>>>(pred0, pred1, pred2, targets, cats, out);
}

// round 17
// speedup vs baseline: 1.1800x; 1.1800x over previous
#include <cuda_runtime.h>
#include <math.h>
#include <stdint.h>

// ---------------------------------------------------------------------------
// YOLO loss, fused single kernel (712 blocks x 256), templated per level.
// R17 = R15 (best) + early target prefetch + simplified single-sync elect.
// ---------------------------------------------------------------------------

#define NBATCH 8
#define MTGT   64
#define NCLS   80
#define NCHAN  85
#define NPAIR  (3 * MTGT * 3)   // 576
#define MAXW   76
#define BMW    3
#define BMWORDS (NBATCH * MAXW * BMW)   // 1824 words

__device__ __constant__ float C_INV[3]  = {0.125f, 0.0625f, 0.03125f};
__device__ __constant__ float C_XYS[3]  = {1.2f, 1.1f, 1.05f};
__device__ __constant__ float C_AW[3][3] = {
    {1.5f, 2.375f, 5.0f},
    {2.25f, 4.75f, 4.5f},
    {4.4375f, 6.0f, 14.34375f}};
__device__ __constant__ float C_AH[3][3] = {
    {2.0f, 4.5f, 3.5f},
    {4.6875f, 3.4375f, 9.125f},
    {3.4375f, 7.59375f, 12.53125f}};

#define NBLK0  542
#define NBLK1  136
#define NBLK2  34
#define NBLK_TOTAL (NBLK0 + NBLK1 + NBLK2)   // 712

// fixed-point accumulators: [0]=iou, [1]=obj_pos, [2]=cls, [3]=obj_neg
__device__ long long g_acc[4] = {0, 0, 0, 0};
__device__ unsigned  g_done = 0;

#define FP_SCALE 1099511627776.0   // 2^40

__device__ __forceinline__ void acc_add(int q, double v) {
    atomicAdd((unsigned long long*)&g_acc[q],
              (unsigned long long)__double2ll_rn(v * FP_SCALE));
}

// ---------------------------------------------------------------------------
__device__ __forceinline__ float softplus_fast(float x) {
    return fmaxf(x, 0.0f) + __logf(1.0f + __expf(-fabsf(x)));
}

struct TPrep {
    float4 corn;
    float4 cwh;
    float  area;
    int    meta;   // bid | ti<<4 | tj<<12 | matchbits<<20
};

// EXACT fp32 (div by pow2 -> exact multiply), same op order as reference.
// Takes pre-loaded raw target values (so the LDGs can be issued early).
__device__ __forceinline__ TPrep prep_vals(int L, float r0, float r1, float r2,
                                           float r3, float r4) {
    float inv = C_INV[L];
    float x1 = r0 * inv;
    float y1 = r1 * inv;
    float x2 = r2 * inv;
    float y2 = r3 * inv;
    int bid  = (int)r4;

    float wx = x2 - x1, wy = y2 - y1;
    float cx = (x1 + x2) * 0.5f, cy = (y1 + y2) * 0.5f;
    int ti = (int)cx, tj = (int)cy;
    float tarea = wx * wy;

    float iou[3];
    #pragma unroll
    for (int a = 0; a < 3; ++a) {
        float aw = C_AW[L][a], ah = C_AH[L][a];
        float inter = fminf(aw, wx) * fminf(ah, wy);
        iou[a] = inter / ((aw * ah + tarea) - inter);   // IEEE div: threshold-critical
    }
    int best = 0;
    if (iou[1] > iou[best]) best = 1;
    if (iou[2] > iou[best]) best = 2;
    int mb = 0;
    #pragma unroll
    for (int a = 0; a < 3; ++a)
        if (iou[a] > 0.213f || a == best) mb |= (1 << a);

    TPrep p;
    p.corn = make_float4(cx - wx * 0.5f, cy - wy * 0.5f,
                         cx + wx * 0.5f, cy + wy * 0.5f);
    p.cwh  = make_float4(cx, cy, wx, wy);
    p.area = tarea;
    p.meta = bid | (ti << 4) | (tj << 12) | (mb << 20);
    return p;
}

__device__ __forceinline__ TPrep prep_one(int L, int t,
                                          const float* __restrict__ targets) {
    return prep_vals(L, targets[t * 5 + 0], targets[t * 5 + 1],
                     targets[t * 5 + 2], targets[t * 5 + 3], targets[t * 5 + 4]);
}

// CIoU (forward)
__device__ __forceinline__ float ciou_f(
    float cx1, float cy1, float w1, float h1,
    float cx2, float cy2, float w2, float h2) {
    float b1x1 = cx1 - 0.5f * w1, b1x2 = cx1 + 0.5f * w1;
    float b1y1 = cy1 - 0.5f * h1, b1y2 = cy1 + 0.5f * h1;
    float b2x1 = cx2 - 0.5f * w2, b2x2 = cx2 + 0.5f * w2;
    float b2y1 = cy2 - 0.5f * h2, b2y2 = cy2 + 0.5f * h2;
    float iw = fminf(b1x2, b2x2) - fmaxf(b1x1, b2x1);
    float ih = fminf(b1y2, b2y2) - fmaxf(b1y1, b2y1);
    float inter = fmaxf(iw, 0.0f) * fmaxf(ih, 0.0f);
    float uni = w1 * h1 + w2 * h2 + 1e-16f - inter;
    float iou = inter / uni;
    float cw = fmaxf(b1x2, b2x2) - fminf(b1x1, b2x1);
    float ch = fmaxf(b1y2, b2y2) - fminf(b1y1, b2y1);
    float c2 = cw * cw + ch * ch + 1e-16f;
    float rho2 = (cx1 - cx2) * (cx1 - cx2) + (cy1 - cy2) * (cy1 - cy2);
    float d = atanf(w2 / h2) - atanf(w1 / h1);
    float v = (float)(4.0 / (M_PI * M_PI)) * d * d;
    float alpha = v / ((1.0f - iou) + v + 1e-16f);
    return iou - (rho2 / c2 + v * alpha);
}

// ---------------------------------------------------------------------------
struct SharedState {
    uint32_t bm[BMWORDS];        // 7.3 KB candidate bitmap
    float4 corn[MTGT];           // by target index (uncompacted)
    float  area[MTGT];
    int    key [MTGT];           // ti | tj<<8 | mb<<16
    int4   pf  [MTGT];           // tight candidate boxes
    int    bid [MTGT];
    uint32_t mask[NBATCH][2];    // per-batch membership (ballot-built)
};

// Per-level flow. All threads of a block share LVL (uniform syncs).
template<int W, int HW, int LVL>
__device__ __forceinline__ float level_flow(
    const float* __restrict__ pred,
    const float* __restrict__ targets,
    int blk, int tid, SharedState& ss) {

    constexpr float s = (LVL == 0) ? 1.2f : ((LVL == 1) ? 1.1f : 1.05f);
    constexpr float half_sm1 = 0.5f * (s - 1.0f);

    // ---- issue the target LDGs FIRST (critical path of the preamble) --------
    float r0 = 0.0f, r1 = 0.0f, r2 = 0.0f, r3 = 0.0f, r4 = 0.0f;
    if (tid < MTGT) {
        const float* tp = targets + tid * 5;
        r0 = tp[0]; r1 = tp[1]; r2 = tp[2]; r3 = tp[3]; r4 = tp[4];
    }

    // ---- decode my cell and ISSUE the obj-logit load --------------------------
    int idx = blk * 256 + tid;
    bool incell = idx < 24 * HW;
    int lc = 0, x = 0, y = 0, a = 0, b = 0, chan = 0;
    float po = 0.0f;
    if (incell) {
        int plane = idx / HW;        // constant divisor -> mul-shift
        lc = idx - plane * HW;
        y = lc / W;
        x = lc - y * W;
        a = plane % 3;
        b = plane / 3;
        chan = plane * (NCHAN * HW);
        po = pred[chan + 4 * HW + lc];   // DRAM latency overlaps preamble
    }

    // ---- preamble phase A ------------------------------------------------------
    if (tid < MTGT) {
        TPrep myp = prep_vals(LVL, r0, r1, r2, r3, r4);
        int bb = myp.meta & 15;

        // TIGHT candidate box: IoU>0.7 => |pred_cx - t_cx| <= (3/14)*tw;
        // cell_x = pred_cx - bx with bx in [-0.1, 1.1].
        float tw = myp.cwh.z, th = myp.cwh.w;
        float cx = myp.cwh.x, cy = myp.cwh.y;
        int xlo = max(0,     (int)floorf(cx - 0.22f * tw - 1.2f));
        int xhi = min(W - 1, (int)ceilf (cx + 0.22f * tw + 0.2f));
        int ylo = max(0,     (int)floorf(cy - 0.22f * th - 1.2f));
        int yhi = min(W - 1, (int)ceilf (cy + 0.22f * th + 0.2f));

        ss.corn[tid] = myp.corn;
        ss.area[tid] = myp.area;
        ss.key [tid] = ((myp.meta >> 4) & 255) | (((myp.meta >> 12) & 255) << 8)
                     | (((myp.meta >> 20) & 7) << 16);
        ss.pf  [tid] = make_int4(xlo, xhi, ylo, yhi);
        ss.bid [tid] = bb;

        int word = tid >> 5;
        int lane = tid & 31;
        #pragma unroll
        for (int j = 0; j < NBATCH; ++j) {
            uint32_t m = __ballot_sync(0xFFFFFFFFu, bb == j);
            if (lane == j) ss.mask[j][word] = m;
        }
    } else {
        uint4* bm4 = reinterpret_cast<uint4*>(ss.bm);
        for (int i = tid - MTGT; i < BMWORDS / 4; i += 192)
            bm4[i] = make_uint4(0u, 0u, 0u, 0u);
    }
    __syncthreads();   // bitmap zeroed, lists + masks + boxes written

    // ---- preamble phase B: ALL 256 threads paint (target, row-quarter) ---------
    {
        int k = tid & 63;
        int q = tid >> 6;          // 0..3
        int4 bx4 = ss.pf[k];
        if (bx4.x <= bx4.y) {
            uint32_t* bmrow = ss.bm + ss.bid[k] * (MAXW * BMW);
            int w0 = bx4.x >> 5, w1 = bx4.y >> 5;
            for (int yy = bx4.z + q; yy <= bx4.w; yy += 4) {
                for (int ww = w0; ww <= w1; ++ww) {
                    int lob = (ww == w0) ? (bx4.x & 31) : 0;
                    int hib = (ww == w1) ? (bx4.y & 31) : 31;
                    uint32_t bits = (hib == 31) ? (~0u << lob)
                                                : (((1u << (hib + 1)) - 1u) & (~0u << lob));
                    atomicOr(&bmrow[yy * BMW + ww], bits);
                }
            }
        }
    }
    float sp = incell ? softplus_fast(po) : 0.0f;   // overlaps painting
    __syncthreads();   // bitmap ready

    // ---- dense cell --------------------------------------------------------------
    float local = 0.0f;
    if (incell) {
        bool zero = false;
        if ((ss.bm[(b * MAXW + y) * BMW + (x >> 5)] >> (x & 31)) & 1u) {
            float p0 = pred[chan + lc];
            float p1 = pred[chan + HW + lc];
            float p2 = pred[chan + 2 * HW + lc];
            float p3 = pred[chan + 3 * HW + lc];

            float bx = __fdividef(1.0f, 1.0f + __expf(-p0)) * s - half_sm1;
            float by = __fdividef(1.0f, 1.0f + __expf(-p1)) * s - half_sm1;
            float pw = __expf(p2) * C_AW[LVL][a];
            float ph = __expf(p3) * C_AH[LVL][a];

            float cxa = bx + (float)x;
            float cya = by + (float)y;
            float bx1 = cxa - 0.5f * pw, bx2 = cxa + 0.5f * pw;
            float by1 = cya - 0.5f * ph, by2 = cya + 0.5f * ph;
            float parea = pw * ph;

            int mykey = x | (y << 8);
            #pragma unroll
            for (int word = 0; word < 2 && !zero; ++word) {
                uint32_t m = ss.mask[b][word];
                int kbase = word << 5;
                while (m) {
                    int k = kbase + __ffs(m) - 1;
                    m &= m - 1u;
                    int4 pf = ss.pf[k];
                    if (x < pf.x || x > pf.y || y < pf.z || y > pf.w) continue;
                    int kk = ss.key[k];
                    if (((kk & 0xFFFF) == mykey) && ((kk >> (16 + a)) & 1)) { zero = true; break; }
                    float4 c  = ss.corn[k];
                    float ix = fminf(bx2, c.z) - fmaxf(bx1, c.x);
                    float iy = fminf(by2, c.w) - fmaxf(by1, c.y);
                    float inter = fmaxf(ix, 0.0f) * fmaxf(iy, 0.0f);
                    float uni   = (parea + ss.area[k] + 1e-16f) - inter;
                    if (inter > 0.7f * uni) { zero = true; break; }
                }
            }
        }
        if (!zero) local = sp;
    }
    return local;
}

// ---------------------------------------------------------------------------
__global__ void __launch_bounds__(256, 8) yolo_fused_kernel(
    const float* __restrict__ pred0,
    const float* __restrict__ pred1,
    const float* __restrict__ pred2,
    const float* __restrict__ targets,
    const int*   __restrict__ cats,
    float* __restrict__ out) {

    int tid  = threadIdx.x;
    int lane = tid & 31;
    int wid  = tid >> 5;

    __shared__ SharedState ss;

    // ---- per-level dense flow (uniform branch per block) ----------------------
    float local;
    if (blockIdx.x >= NBLK0 + NBLK1)
        local = level_flow<19, 361, 2>(pred2, targets,
                                       blockIdx.x - (NBLK0 + NBLK1), tid, ss);
    else if (blockIdx.x >= NBLK0)
        local = level_flow<38, 1444, 1>(pred1, targets, blockIdx.x - NBLK0, tid, ss);
    else
        local = level_flow<76, 5776, 0>(pred0, targets, blockIdx.x, tid, ss);

    // ---- obj_neg block reduce: fp32 intra-warp, fp64 across warps, 1 atomic ----
    {
        float v = local;
        #pragma unroll
        for (int o = 16; o > 0; o >>= 1)
            v += __shfl_down_sync(0xFFFFFFFFu, v, o);
        __shared__ double wsum[8];
        if (lane == 0) wsum[wid] = (double)v;
        __syncthreads();
        if (tid == 0) {
            double t2 = 0.0;
            #pragma unroll
            for (int i = 0; i < 8; ++i) t2 += wsum[i];
            acc_add(3, t2);          // deterministic integer atomic
        }
    }

    // ---- positives: one warp per (L,t,a) pair (blocks 0..71) --------------------
    int gw = blockIdx.x * 8 + wid;
    if (gw < NPAIR) {
        int FL  = gw / (MTGT * 3);
        int rem = gw % (MTGT * 3);
        int t   = rem / 3;
        int a2  = rem % 3;

        TPrep pp = prep_one(FL, t, targets);   // uniform across lanes
        bool matched = (pp.meta >> (20 + a2)) & 1;

        if (matched) {
            int bid = pp.meta & 15;
            int ti  = (pp.meta >> 4) & 255;
            int tj  = (pp.meta >> 12) & 255;
            const float* fp = (FL == 0) ? pred0 : ((FL == 1) ? pred1 : pred2);
            int fw  = (FL == 0) ? 76 : ((FL == 1) ? 38 : 19);
            int fhw = fw * fw;
            int base = ((bid * 3 + a2) * NCHAN) * fhw + tj * fw + ti;

            float cls_acc = 0.0f;
            int cat = cats[t] - 1;
            for (int c = lane; c < NCLS; c += 32) {
                float xl  = fp[base + (5 + c) * fhw];
                float bce = softplus_fast(xl);
                if (c == cat) bce -= xl;
                cls_acc += bce;
            }
            #pragma unroll
            for (int o = 16; o > 0; o >>= 1)
                cls_acc += __shfl_down_sync(0xFFFFFFFFu, cls_acc, o);

            if (lane == 0) {
                float fs  = C_XYS[FL];
                float fhs = 0.5f * (fs - 1.0f);
                float p0 = fp[base];
                float p1 = fp[base + fhw];
                float p2 = fp[base + 2 * fhw];
                float p3 = fp[base + 3 * fhw];
                float pob = fp[base + 4 * fhw];

                float bx = __fdividef(1.0f, 1.0f + __expf(-p0)) * fs - fhs;
                float by = __fdividef(1.0f, 1.0f + __expf(-p1)) * fs - fhs;
                float pw = __expf(p2) * C_AW[FL][a2];
                float ph = __expf(p3) * C_AH[FL][a2];

                float fx = pp.cwh.x - (float)ti;
                float fy = pp.cwh.y - (float)tj;
                double iou_d = (double)(1.0f - ciou_f(bx, by, pw, ph, fx, fy,
                                                      pp.cwh.z, pp.cwh.w));
                double obj_d = (double)(softplus_fast(pob) - pob);
                acc_add(0, iou_d);
                acc_add(1, obj_d);
                acc_add(2, (double)cls_acc);
            }
        }
    }

    // ---- single-sync elect: tid0 alone continues --------------------------------
    __syncthreads();   // all warps of this block have issued their acc atomics
    if (tid != 0) return;
    __threadfence();
    unsigned old = atomicAdd(&g_done, 1u);
    if (old == NBLK_TOTAL - 1) {
        __threadfence();
        volatile long long* acc = g_acc;
        double iou = (double)acc[0] / FP_SCALE;
        double obj = (double)acc[1] / FP_SCALE;
        double cls = (double)acc[2] / FP_SCALE;
        double neg = (double)acc[3] / FP_SCALE;
        out[0] = (float)(0.07 * iou);
        out[1] = (float)(obj + neg);
        out[2] = (float)(cls);
        g_acc[0] = 0; g_acc[1] = 0; g_acc[2] = 0; g_acc[3] = 0;
        __threadfence();
        g_done = 0;
    }
}

// ---------------------------------------------------------------------------
extern "C" void kernel_launch(void* const* d_in, const int* in_sizes, int n_in,
                              void* d_out, int out_size) {
    const float* pred0   = (const float*)d_in[0];
    const float* pred1   = (const float*)d_in[1];
    const float* pred2   = (const float*)d_in[2];
    const float* targets = (const float*)d_in[3];
    const int*   cats    = (const int*)  d_in[4];
    float* out = (float*)d_out;

    yolo_fused_kernel<<<NBLK_TOTAL, 256>>>(pred0, pred1, pred2, targets, cats, out);
}